// round 11
// baseline (speedup 1.0000x reference)
#include <cuda_runtime.h>
#include <stdint.h>

#define NROWS 8192
#define DDIM  1024
// jax.random.key(42) under threefry2x32: key = (0, 42)
#define TF_K1  42u
#define TF_KS2 (42u ^ 0x1BD11BDAu)

// Scratch (device globals — no allocation allowed)
__device__ unsigned long long g_pos[NROWS];
__device__ unsigned long long g_neg[NROWS];
__device__ float g_per[NROWS];
__device__ float g_vld[NROWS];
// Opaque 1: read through volatile so ptxas cannot constant-fold the IMADs
// that carry the threefry adds on the fma pipe (alu pipe is the bottleneck).
__device__ uint32_t g_one = 1u;

// add via IMAD (fma pipe): a + b  ==  b*one + a
#define MADD(a, b) __extension__({ uint32_t _r;                              \
    asm("mad.lo.u32 %0, %1, %2, %3;" : "=r"(_r) : "r"(b), "r"(one), "r"(a)); \
    _r; })
// add-immediate via IMAD (fma pipe): a + K  ==  one*K + a
#define MADDC(a, K) __extension__({ uint32_t _r;                             \
    asm("mad.lo.u32 %0, %1, %2, %3;" : "=r"(_r) : "r"(one), "n"(K), "r"(a)); \
    _r; })

// Threefry-2x32, 20 rounds — exact JAX semantics, adds steered to fma pipe.
// Key = (0, 42): the x0 += K0 schedule adds are +0 and elided.
__device__ __forceinline__ void threefry(uint32_t x1, uint32_t one,
                                         uint32_t& o0, uint32_t& o1) {
    uint32_t x0 = 0u;
    x1 = MADDC(x1, TF_K1);
#define TF_RND(r) { x0 = MADD(x0, x1); x1 = __funnelshift_l(x1, x1, r); x1 ^= x0; }
    TF_RND(13) TF_RND(15) TF_RND(26) TF_RND(6)
    x0 = MADDC(x0, TF_K1);        x1 = MADDC(x1, TF_KS2 + 1u);
    TF_RND(17) TF_RND(29) TF_RND(16) TF_RND(24)
    x0 = MADDC(x0, TF_KS2);       x1 = MADDC(x1, 2u);
    TF_RND(13) TF_RND(15) TF_RND(26) TF_RND(6)
    /* x0 += K0 (=0) elided */    x1 = MADDC(x1, TF_K1 + 3u);
    TF_RND(17) TF_RND(29) TF_RND(16) TF_RND(24)
    x0 = MADDC(x0, TF_K1);        x1 = MADDC(x1, TF_KS2 + 4u);
    TF_RND(13) TF_RND(15) TF_RND(26) TF_RND(6)
    x0 = MADDC(x0, TF_KS2);       x1 = MADDC(x1, 5u);
#undef TF_RND
    o0 = x0; o1 = x1;
}

// Kernel 1: one block per anchor row. JAX partitionable threefry stream:
// element i of the (N,N) gumbel matrix uses counter (hi=0, lo=i) and
// 32-bit draw = out0 ^ out1. Gumbel-argmax == argmax of (bits >> 9) with
// first-index tie-break, done via packed u64 max (no logs). Pack is
// (bits>>9)<<32 | ~c; since c<8192, ~c!=0, so packed==0 <=> no candidate.
__global__ void __launch_bounds__(256) argmax_kernel(const int* __restrict__ cat) {
    __shared__ uint8_t s_cat[NROWS];
    __shared__ unsigned long long s_red[2][8];
    const int tid = threadIdx.x;
    const int r = blockIdx.x;
    const uint32_t one = *(volatile const uint32_t*)&g_one;

    for (int i = tid; i < NROWS; i += 256) s_cat[i] = (uint8_t)cat[i];
    __syncthreads();

    const uint8_t cat_r = s_cat[r];
    unsigned long long bp = 0ull, bn = 0ull;
    const uint32_t base = (uint32_t)r * 8192u;

    #pragma unroll 8
    for (int k = 0; k < 32; k++) {
        const uint32_t c = (uint32_t)tid + (uint32_t)k * 256u;
        uint32_t o0, o1;
        threefry(base + c, one, o0, o1);
        const uint32_t bits = o0 ^ o1;
        const unsigned long long p =
            ((unsigned long long)(bits >> 9) << 32) | (uint32_t)(~c);
        const uint8_t cc = s_cat[c];
        if (cc == cat_r) { if (c != (uint32_t)r && p > bp) bp = p; }
        else             { if (p > bn) bn = p; }
    }

    // warp reduce (u64 max)
    #pragma unroll
    for (int o = 16; o; o >>= 1) {
        unsigned long long v;
        v = __shfl_down_sync(0xffffffffu, bp, o); if (v > bp) bp = v;
        v = __shfl_down_sync(0xffffffffu, bn, o); if (v > bn) bn = v;
    }
    const int lane = tid & 31, w = tid >> 5;
    if (lane == 0) { s_red[0][w] = bp; s_red[1][w] = bn; }
    __syncthreads();
    if (tid < 2) {
        unsigned long long best = s_red[tid][0];
        #pragma unroll
        for (int i = 1; i < 8; i++) if (s_red[tid][i] > best) best = s_red[tid][i];
        if (tid == 0) g_pos[r] = best; else g_neg[r] = best;
    }
}

// Kernel 2: per-anchor triplet margin term. One block per row, float4 loads.
__global__ void __launch_bounds__(256) dist_kernel(const float* __restrict__ eeg,
                                                   const float* __restrict__ text) {
    const int row = blockIdx.x;
    const unsigned long long pp = g_pos[row];
    const unsigned long long np = g_neg[row];
    const bool valid = (pp != 0ull) && (np != 0ull);
    const uint32_t pidx = valid ? ~(uint32_t)pp : 0u;
    const uint32_t nidx = valid ? ~(uint32_t)np : 0u;

    const int t = threadIdx.x;
    const float4 av = ((const float4*)(eeg  + (size_t)row  * DDIM))[t];
    const float4 pv = ((const float4*)(text + (size_t)pidx * DDIM))[t];
    const float4 nv = ((const float4*)(text + (size_t)nidx * DDIM))[t];

    float sp, sn;
    {
        float d0 = av.x - pv.x + 1e-6f, d1 = av.y - pv.y + 1e-6f;
        float d2 = av.z - pv.z + 1e-6f, d3 = av.w - pv.w + 1e-6f;
        sp = d0*d0 + d1*d1 + d2*d2 + d3*d3;
        d0 = av.x - nv.x + 1e-6f; d1 = av.y - nv.y + 1e-6f;
        d2 = av.z - nv.z + 1e-6f; d3 = av.w - nv.w + 1e-6f;
        sn = d0*d0 + d1*d1 + d2*d2 + d3*d3;
    }
    #pragma unroll
    for (int o = 16; o; o >>= 1) {
        sp += __shfl_down_sync(0xffffffffu, sp, o);
        sn += __shfl_down_sync(0xffffffffu, sn, o);
    }
    __shared__ float s_p[8], s_n[8];
    if ((t & 31) == 0) { s_p[t >> 5] = sp; s_n[t >> 5] = sn; }
    __syncthreads();
    if (t == 0) {
        float tp = 0.f, tn = 0.f;
        #pragma unroll
        for (int i = 0; i < 8; i++) { tp += s_p[i]; tn += s_n[i]; }
        const float per = fmaxf(sqrtf(tp) - sqrtf(tn) + 0.2f, 0.0f);
        g_per[row] = valid ? per : 0.0f;
        g_vld[row] = valid ? 1.0f : 0.0f;
    }
}

// Kernel 3: deterministic final reduction
__global__ void __launch_bounds__(256) final_kernel(float* __restrict__ out) {
    __shared__ float s_s[256], s_c[256];
    float s = 0.f, c = 0.f;
    for (int i = threadIdx.x; i < NROWS; i += 256) { s += g_per[i]; c += g_vld[i]; }
    s_s[threadIdx.x] = s; s_c[threadIdx.x] = c;
    __syncthreads();
    for (int o = 128; o; o >>= 1) {
        if (threadIdx.x < o) {
            s_s[threadIdx.x] += s_s[threadIdx.x + o];
            s_c[threadIdx.x] += s_c[threadIdx.x + o];
        }
        __syncthreads();
    }
    if (threadIdx.x == 0) {
        const float cnt = s_c[0];
        out[0] = (cnt > 0.f) ? (s_s[0] / fmaxf(cnt, 1.f)) : 0.0f;
    }
}

extern "C" void kernel_launch(void* const* d_in, const int* in_sizes, int n_in,
                              void* d_out, int out_size) {
    const float* eeg  = (const float*)d_in[0];
    const float* text = (const float*)d_in[1];
    const int*   cat  = (const int*)d_in[2];
    float* out = (float*)d_out;
    argmax_kernel<<<NROWS, 256>>>(cat);
    dist_kernel<<<NROWS, 256>>>(eeg, text);
    final_kernel<<<1, 256>>>(out);
}

// round 13
// speedup vs baseline: 1.0664x; 1.0664x over previous
#include <cuda_runtime.h>
#include <stdint.h>

#define NROWS 8192
#define DDIM  1024
// jax.random.key(42) under threefry2x32: key = (0, 42)
#define TF_K1  42u
#define TF_KS2 (42u ^ 0x1BD11BDAu)

// Scratch (device globals — no allocation allowed)
__device__ unsigned long long g_pos[NROWS];
__device__ unsigned long long g_neg[NROWS];
__device__ float g_per[NROWS];
__device__ float g_vld[NROWS];
// Opaque 1: volatile load defeats constant-folding of the IMAD-carried adds.
__device__ uint32_t g_one = 1u;

// add via IMAD (fma pipe): a + b  ==  b*one + a
#define MADD(a, b) __extension__({ uint32_t _r;                              \
    asm("mad.lo.u32 %0, %1, %2, %3;" : "=r"(_r) : "r"(b), "r"(one), "r"(a)); \
    _r; })
// add-immediate via IMAD (fma pipe): a + K  ==  one*K + a
#define MADDC(a, K) __extension__({ uint32_t _r;                             \
    asm("mad.lo.u32 %0, %1, %2, %3;" : "=r"(_r) : "r"(one), "n"(K), "r"(a)); \
    _r; })

// Threefry-2x32, 20 rounds, key (0,42) — exact JAX semantics. Input must
// already include the +42 first key add (folded into the caller's base).
// Returns o0 ^ o1 (JAX partitionable 32-bit draw). Round 1's x0 add is
// elided since x0 starts at 0.
__device__ __forceinline__ uint32_t tf_bits(uint32_t x1, uint32_t one) {
    uint32_t x0 = x1;                                  // r1: x0 = 0 + x1
    x1 = __funnelshift_l(x1, x1, 13) ^ x0;
#define TF_RND(r) { x0 = MADD(x0, x1); x1 = __funnelshift_l(x1, x1, r); x1 ^= x0; }
    TF_RND(15) TF_RND(26) TF_RND(6)                    // r2-r4
    x0 = MADDC(x0, TF_K1);   x1 = MADDC(x1, TF_KS2 + 1u);
    TF_RND(17) TF_RND(29) TF_RND(16) TF_RND(24)
    x0 = MADDC(x0, TF_KS2);  x1 = MADDC(x1, 2u);
    TF_RND(13) TF_RND(15) TF_RND(26) TF_RND(6)
    /* x0 += K0 (=0) elided */ x1 = MADDC(x1, TF_K1 + 3u);
    TF_RND(17) TF_RND(29) TF_RND(16) TF_RND(24)
    x0 = MADDC(x0, TF_K1);   x1 = MADDC(x1, TF_KS2 + 4u);
    TF_RND(13) TF_RND(15) TF_RND(26) TF_RND(6)
    x0 = MADDC(x0, TF_KS2);  x1 = MADDC(x1, 5u);
#undef TF_RND
    return x0 ^ x1;
}

// Kernel 1: one block per anchor row. Per-element u32 accumulator packs the
// 23-bit gumbel key with (31-k): max == argmax with smallest-c tie-break
// inside a thread. Classification via pre-XORed smem categories:
//   t = cat[c]^cat_r (self entry = 0x80 sentinel; cats < 40 so unambiguous)
//   pos: t == 0   neg: (t & 0x7F) != 0   (self excluded from both)
// Repacked to u64 (key<<32 | ~c) once per thread for exact cross-thread
// first-index tie-break; 0 sentinel == no candidate.
__global__ void __launch_bounds__(256, 6) argmax_kernel(const int* __restrict__ cat) {
    __shared__ uint8_t s_t[NROWS];
    __shared__ unsigned long long s_red[2][8];
    const int tid = threadIdx.x;
    const int r = blockIdx.x;
    const uint32_t one = *(volatile const uint32_t*)&g_one;

    const uint32_t cat_r = (uint32_t)cat[r];
    for (int i = tid; i < NROWS; i += 256) {
        uint32_t v = (uint32_t)cat[i] ^ cat_r;
        s_t[i] = (uint8_t)((i == r) ? 0x80u : v);
    }
    __syncthreads();

    uint32_t bp32 = 0u, bn32 = 0u;
    // base folds the row offset, thread column and the +42 key add
    const uint32_t base42 = (uint32_t)r * 8192u + (uint32_t)tid + TF_K1;

    #pragma unroll 8
    for (int k = 0; k < 32; k++) {
        const uint32_t bits = tf_bits(base42 + (uint32_t)k * 256u, one);
        // p32 = (bits>>9)<<5 | (31-k); key-major, smaller k wins ties
        const uint32_t p32 = ((bits >> 4) & 0xFFFFFFE0u) | (31u - (uint32_t)k);
        const uint32_t t = (uint32_t)s_t[tid + k * 256];
        asm("{\n\t"
            ".reg .pred pp, pn;\n\t"
            ".reg .u32 t7;\n\t"
            "setp.eq.u32 pp, %2, 0;\n\t"
            "and.b32 t7, %2, 0x7F;\n\t"
            "setp.ne.u32 pn, t7, 0;\n\t"
            "@pp max.u32 %0, %0, %3;\n\t"
            "@pn max.u32 %1, %1, %3;\n\t"
            "}"
            : "+r"(bp32), "+r"(bn32) : "r"(t), "r"(p32));
    }

    // repack to u64 with full column index for exact global tie-break
    unsigned long long bp = 0ull, bn = 0ull;
    if (bp32) {
        const uint32_t kk = 31u - (bp32 & 31u);
        const uint32_t cb = (uint32_t)tid + (kk << 8);
        bp = ((unsigned long long)(bp32 >> 5) << 32) | (uint32_t)(~cb);
    }
    if (bn32) {
        const uint32_t kk = 31u - (bn32 & 31u);
        const uint32_t cb = (uint32_t)tid + (kk << 8);
        bn = ((unsigned long long)(bn32 >> 5) << 32) | (uint32_t)(~cb);
    }

    // warp reduce (u64 max)
    #pragma unroll
    for (int o = 16; o; o >>= 1) {
        unsigned long long v;
        v = __shfl_down_sync(0xffffffffu, bp, o); if (v > bp) bp = v;
        v = __shfl_down_sync(0xffffffffu, bn, o); if (v > bn) bn = v;
    }
    const int lane = tid & 31, w = tid >> 5;
    if (lane == 0) { s_red[0][w] = bp; s_red[1][w] = bn; }
    __syncthreads();
    if (tid < 2) {
        unsigned long long best = s_red[tid][0];
        #pragma unroll
        for (int i = 1; i < 8; i++) if (s_red[tid][i] > best) best = s_red[tid][i];
        if (tid == 0) g_pos[r] = best; else g_neg[r] = best;
    }
}

// Kernel 2: per-anchor triplet margin term. One block per row, float4 loads.
__global__ void __launch_bounds__(256) dist_kernel(const float* __restrict__ eeg,
                                                   const float* __restrict__ text) {
    const int row = blockIdx.x;
    const unsigned long long pp = g_pos[row];
    const unsigned long long np = g_neg[row];
    const bool valid = (pp != 0ull) && (np != 0ull);
    const uint32_t pidx = valid ? (~(uint32_t)pp) & 0x1FFFu : 0u;
    const uint32_t nidx = valid ? (~(uint32_t)np) & 0x1FFFu : 0u;

    const int t = threadIdx.x;
    const float4 av = ((const float4*)(eeg  + (size_t)row  * DDIM))[t];
    const float4 pv = ((const float4*)(text + (size_t)pidx * DDIM))[t];
    const float4 nv = ((const float4*)(text + (size_t)nidx * DDIM))[t];

    float sp, sn;
    {
        float d0 = av.x - pv.x + 1e-6f, d1 = av.y - pv.y + 1e-6f;
        float d2 = av.z - pv.z + 1e-6f, d3 = av.w - pv.w + 1e-6f;
        sp = d0*d0 + d1*d1 + d2*d2 + d3*d3;
        d0 = av.x - nv.x + 1e-6f; d1 = av.y - nv.y + 1e-6f;
        d2 = av.z - nv.z + 1e-6f; d3 = av.w - nv.w + 1e-6f;
        sn = d0*d0 + d1*d1 + d2*d2 + d3*d3;
    }
    #pragma unroll
    for (int o = 16; o; o >>= 1) {
        sp += __shfl_down_sync(0xffffffffu, sp, o);
        sn += __shfl_down_sync(0xffffffffu, sn, o);
    }
    __shared__ float s_p[8], s_n[8];
    if ((t & 31) == 0) { s_p[t >> 5] = sp; s_n[t >> 5] = sn; }
    __syncthreads();
    if (t == 0) {
        float tp = 0.f, tn = 0.f;
        #pragma unroll
        for (int i = 0; i < 8; i++) { tp += s_p[i]; tn += s_n[i]; }
        const float per = fmaxf(sqrtf(tp) - sqrtf(tn) + 0.2f, 0.0f);
        g_per[row] = valid ? per : 0.0f;
        g_vld[row] = valid ? 1.0f : 0.0f;
    }
}

// Kernel 3: deterministic final reduction
__global__ void __launch_bounds__(256) final_kernel(float* __restrict__ out) {
    __shared__ float s_s[256], s_c[256];
    float s = 0.f, c = 0.f;
    for (int i = threadIdx.x; i < NROWS; i += 256) { s += g_per[i]; c += g_vld[i]; }
    s_s[threadIdx.x] = s; s_c[threadIdx.x] = c;
    __syncthreads();
    for (int o = 128; o; o >>= 1) {
        if (threadIdx.x < o) {
            s_s[threadIdx.x] += s_s[threadIdx.x + o];
            s_c[threadIdx.x] += s_c[threadIdx.x + o];
        }
        __syncthreads();
    }
    if (threadIdx.x == 0) {
        const float cnt = s_c[0];
        out[0] = (cnt > 0.f) ? (s_s[0] / fmaxf(cnt, 1.f)) : 0.0f;
    }
}

extern "C" void kernel_launch(void* const* d_in, const int* in_sizes, int n_in,
                              void* d_out, int out_size) {
    const float* eeg  = (const float*)d_in[0];
    const float* text = (const float*)d_in[1];
    const int*   cat  = (const int*)d_in[2];
    float* out = (float*)d_out;
    argmax_kernel<<<NROWS, 256>>>(cat);
    dist_kernel<<<NROWS, 256>>>(eeg, text);
    final_kernel<<<1, 256>>>(out);
}

// round 15
// speedup vs baseline: 1.0747x; 1.0077x over previous
#include <cuda_runtime.h>
#include <stdint.h>

#define NROWS 8192
#define DDIM  1024
// jax.random.key(42) under threefry2x32: key = (0, 42)
#define TF_K1  42u
#define TF_KS2 (42u ^ 0x1BD11BDAu)

// Scratch (device globals — no allocation allowed)
__device__ unsigned long long g_pos[NROWS];
__device__ unsigned long long g_neg[NROWS];
__device__ float g_per[NROWS];
__device__ float g_vld[NROWS];

// Threefry-2x32, 20 rounds, key (0,42) — exact JAX semantics. Input must
// already include the +42 first key add (folded into the caller's base).
// Plain C++ adds: ptxas fuses the x0-side key-schedule adds into 3-input
// IADD3 with the following round's add, and auto-balances IMAD<->IADD3
// across the fma/alu pipes. Returns o0 ^ o1 (JAX partitionable draw).
__device__ __forceinline__ uint32_t tf_bits(uint32_t x1) {
    uint32_t x0 = x1;                                  // r1: x0 = 0 + x1
    x1 = __funnelshift_l(x1, x1, 13) ^ x0;
#define TF_RND(r) { x0 += x1; x1 = __funnelshift_l(x1, x1, r); x1 ^= x0; }
    TF_RND(15) TF_RND(26) TF_RND(6)                    // r2-r4
    x0 += TF_K1;   x1 += TF_KS2 + 1u;
    TF_RND(17) TF_RND(29) TF_RND(16) TF_RND(24)
    x0 += TF_KS2;  x1 += 2u;
    TF_RND(13) TF_RND(15) TF_RND(26) TF_RND(6)
    /* x0 += K0 (=0) elided */ x1 += TF_K1 + 3u;
    TF_RND(17) TF_RND(29) TF_RND(16) TF_RND(24)
    x0 += TF_K1;   x1 += TF_KS2 + 4u;
    TF_RND(13) TF_RND(15) TF_RND(26) TF_RND(6)
    x0 += TF_KS2;  x1 += 5u;
#undef TF_RND
    return x0 ^ x1;
}

// Kernel 1: one block per anchor row. Per-element u32 accumulator packs the
// 23-bit gumbel key with (31-k): max == argmax with smallest-c tie-break
// inside a thread. Classification via 3-state code byte in smem:
//   0 = positive (same category, not self), 1 = self, 2 = negative
// Repacked to u64 (key<<32 | ~c) once per thread for exact cross-thread
// first-index tie-break; 0 sentinel == no candidate.
__global__ void __launch_bounds__(256, 6) argmax_kernel(const int* __restrict__ cat) {
    __shared__ uint8_t s_t[NROWS];
    __shared__ unsigned long long s_red[2][8];
    const int tid = threadIdx.x;
    const int r = blockIdx.x;

    const int cat_r = cat[r];
    for (int i = tid; i < NROWS; i += 256) {
        uint32_t code = (cat[i] == cat_r) ? 0u : 2u;
        s_t[i] = (uint8_t)((i == r) ? 1u : code);
    }
    __syncthreads();

    uint32_t bp32 = 0u, bn32 = 0u;
    // base folds the row offset, thread column and the +42 key add
    const uint32_t base42 = (uint32_t)r * 8192u + (uint32_t)tid + TF_K1;

    #pragma unroll 8
    for (int k = 0; k < 32; k++) {
        const uint32_t bits = tf_bits(base42 + (uint32_t)k * 256u);
        // p32 = (bits>>9)<<5 | (31-k); key-major, smaller k wins ties
        const uint32_t p32 = ((bits >> 4) & 0xFFFFFFE0u) | (31u - (uint32_t)k);
        const uint32_t t = (uint32_t)s_t[tid + k * 256];
        if (t == 0u) bp32 = (p32 > bp32) ? p32 : bp32;
        if (t >= 2u) bn32 = (p32 > bn32) ? p32 : bn32;
    }

    // repack to u64 with full column index for exact global tie-break
    unsigned long long bp = 0ull, bn = 0ull;
    if (bp32) {
        const uint32_t kk = 31u - (bp32 & 31u);
        const uint32_t cb = (uint32_t)tid + (kk << 8);
        bp = ((unsigned long long)(bp32 >> 5) << 32) | (uint32_t)(~cb);
    }
    if (bn32) {
        const uint32_t kk = 31u - (bn32 & 31u);
        const uint32_t cb = (uint32_t)tid + (kk << 8);
        bn = ((unsigned long long)(bn32 >> 5) << 32) | (uint32_t)(~cb);
    }

    // warp reduce (u64 max)
    #pragma unroll
    for (int o = 16; o; o >>= 1) {
        unsigned long long v;
        v = __shfl_down_sync(0xffffffffu, bp, o); if (v > bp) bp = v;
        v = __shfl_down_sync(0xffffffffu, bn, o); if (v > bn) bn = v;
    }
    const int lane = tid & 31, w = tid >> 5;
    if (lane == 0) { s_red[0][w] = bp; s_red[1][w] = bn; }
    __syncthreads();
    if (tid < 2) {
        unsigned long long best = s_red[tid][0];
        #pragma unroll
        for (int i = 1; i < 8; i++) if (s_red[tid][i] > best) best = s_red[tid][i];
        if (tid == 0) g_pos[r] = best; else g_neg[r] = best;
    }
}

// Kernel 2: per-anchor triplet margin term. One block per row, float4 loads.
__global__ void __launch_bounds__(256) dist_kernel(const float* __restrict__ eeg,
                                                   const float* __restrict__ text) {
    const int row = blockIdx.x;
    const unsigned long long pp = g_pos[row];
    const unsigned long long np = g_neg[row];
    const bool valid = (pp != 0ull) && (np != 0ull);
    const uint32_t pidx = valid ? (~(uint32_t)pp) & 0x1FFFu : 0u;
    const uint32_t nidx = valid ? (~(uint32_t)np) & 0x1FFFu : 0u;

    const int t = threadIdx.x;
    const float4 av = ((const float4*)(eeg  + (size_t)row  * DDIM))[t];
    const float4 pv = ((const float4*)(text + (size_t)pidx * DDIM))[t];
    const float4 nv = ((const float4*)(text + (size_t)nidx * DDIM))[t];

    float sp, sn;
    {
        float d0 = av.x - pv.x + 1e-6f, d1 = av.y - pv.y + 1e-6f;
        float d2 = av.z - pv.z + 1e-6f, d3 = av.w - pv.w + 1e-6f;
        sp = d0*d0 + d1*d1 + d2*d2 + d3*d3;
        d0 = av.x - nv.x + 1e-6f; d1 = av.y - nv.y + 1e-6f;
        d2 = av.z - nv.z + 1e-6f; d3 = av.w - nv.w + 1e-6f;
        sn = d0*d0 + d1*d1 + d2*d2 + d3*d3;
    }
    #pragma unroll
    for (int o = 16; o; o >>= 1) {
        sp += __shfl_down_sync(0xffffffffu, sp, o);
        sn += __shfl_down_sync(0xffffffffu, sn, o);
    }
    __shared__ float s_p[8], s_n[8];
    if ((t & 31) == 0) { s_p[t >> 5] = sp; s_n[t >> 5] = sn; }
    __syncthreads();
    if (t == 0) {
        float tp = 0.f, tn = 0.f;
        #pragma unroll
        for (int i = 0; i < 8; i++) { tp += s_p[i]; tn += s_n[i]; }
        const float per = fmaxf(sqrtf(tp) - sqrtf(tn) + 0.2f, 0.0f);
        g_per[row] = valid ? per : 0.0f;
        g_vld[row] = valid ? 1.0f : 0.0f;
    }
}

// Kernel 3: deterministic final reduction
__global__ void __launch_bounds__(256) final_kernel(float* __restrict__ out) {
    __shared__ float s_s[256], s_c[256];
    float s = 0.f, c = 0.f;
    for (int i = threadIdx.x; i < NROWS; i += 256) { s += g_per[i]; c += g_vld[i]; }
    s_s[threadIdx.x] = s; s_c[threadIdx.x] = c;
    __syncthreads();
    for (int o = 128; o; o >>= 1) {
        if (threadIdx.x < o) {
            s_s[threadIdx.x] += s_s[threadIdx.x + o];
            s_c[threadIdx.x] += s_c[threadIdx.x + o];
        }
        __syncthreads();
    }
    if (threadIdx.x == 0) {
        const float cnt = s_c[0];
        out[0] = (cnt > 0.f) ? (s_s[0] / fmaxf(cnt, 1.f)) : 0.0f;
    }
}

extern "C" void kernel_launch(void* const* d_in, const int* in_sizes, int n_in,
                              void* d_out, int out_size) {
    const float* eeg  = (const float*)d_in[0];
    const float* text = (const float*)d_in[1];
    const int*   cat  = (const int*)d_in[2];
    float* out = (float*)d_out;
    argmax_kernel<<<NROWS, 256>>>(cat);
    dist_kernel<<<NROWS, 256>>>(eeg, text);
    final_kernel<<<1, 256>>>(out);
}